// round 9
// baseline (speedup 1.0000x reference)
#include <cuda_runtime.h>
#include <cuda_fp16.h>
#include <math.h>
#include <cstdint>

// Problem constants
#define B_ 2
#define S_ 2048
#define D_ 4096
#define H_ 32
#define KV_ 8
#define HD_ 128

// ---------------------------------------------------------------------------
// Scratch (static __device__ per allocation rules)
// ---------------------------------------------------------------------------
__device__ float g_Q[(size_t)B_ * H_ * S_ * HD_];    // [B,H,S,HD] fp32 pre-rope
__device__ float g_K[(size_t)B_ * KV_ * S_ * HD_];
__device__ float g_cos[(size_t)B_ * S_ * 64];
__device__ float g_sin[(size_t)B_ * S_ * 64];
// fp16 tensors
__device__ __half g_hsH[(size_t)B_ * S_ * D_];
__device__ __half g_WqH[(size_t)H_ * HD_ * D_];
__device__ __half g_WkH[(size_t)KV_ * HD_ * D_];
__device__ __half g_WvH[(size_t)KV_ * HD_ * D_];
__device__ __half g_WoH[(size_t)D_ * H_ * HD_];
__device__ __half g_QH[(size_t)B_ * H_ * S_ * HD_];  // roped, pre-scaled
__device__ __half g_KH[(size_t)B_ * KV_ * S_ * HD_]; // roped
__device__ __half g_VH[(size_t)B_ * KV_ * S_ * HD_]; // from GEMM epilogue
__device__ __half g_AOH[(size_t)B_ * S_ * H_ * HD_]; // flash out [B,S,H,HD]

// ---------------------------------------------------------------------------
// Helpers
// ---------------------------------------------------------------------------
__device__ __forceinline__ uint32_t smem_u32(const void* p) {
    uint32_t a;
    asm("{ .reg .u64 t; cvta.to.shared.u64 t, %1; cvt.u32.u64 %0, t; }"
        : "=r"(a) : "l"(p));
    return a;
}
__device__ __forceinline__ uint32_t h2_as_u32(__half2 h) {
    union { __half2 h; uint32_t u; } cvt;
    cvt.h = h;
    return cvt.u;
}
__device__ __forceinline__ void cp_async16(uint32_t saddr, const void* g) {
    asm volatile("cp.async.cg.shared.global [%0], [%1], 16;" :: "r"(saddr), "l"(g));
}
#define CP_COMMIT() asm volatile("cp.async.commit_group;" ::: "memory")
template <int N>
__device__ __forceinline__ void cp_wait() {
    asm volatile("cp.async.wait_group %0;" :: "n"(N) : "memory");
}
__device__ __forceinline__ void ldsm_x4(uint32_t* r, uint32_t addr) {
    asm volatile("ldmatrix.sync.aligned.m8n8.x4.shared.b16 {%0,%1,%2,%3}, [%4];"
                 : "=r"(r[0]), "=r"(r[1]), "=r"(r[2]), "=r"(r[3]) : "r"(addr));
}
__device__ __forceinline__ void ldsm_x4_t(uint32_t* r, uint32_t addr) {
    asm volatile("ldmatrix.sync.aligned.m8n8.x4.trans.shared.b16 {%0,%1,%2,%3}, [%4];"
                 : "=r"(r[0]), "=r"(r[1]), "=r"(r[2]), "=r"(r[3]) : "r"(addr));
}
__device__ __forceinline__ void mma16816(float* c, const uint32_t* a, const uint32_t* b) {
    asm volatile(
        "mma.sync.aligned.m16n8k16.row.col.f32.f16.f16.f32 "
        "{%0,%1,%2,%3}, {%4,%5,%6,%7}, {%8,%9}, {%0,%1,%2,%3};"
        : "+f"(c[0]), "+f"(c[1]), "+f"(c[2]), "+f"(c[3])
        : "r"(a[0]), "r"(a[1]), "r"(a[2]), "r"(a[3]), "r"(b[0]), "r"(b[1]));
}

// ---------------------------------------------------------------------------
// fp32 -> fp16 conversion (4 elems/thread)
// ---------------------------------------------------------------------------
__global__ void f32_to_f16_kernel(const float* __restrict__ in,
                                  __half* __restrict__ out, int n4) {
    int i = blockIdx.x * blockDim.x + threadIdx.x;
    if (i >= n4) return;
    float4 v = *(const float4*)(in + (size_t)i * 4);
    __half2* o = (__half2*)(out + (size_t)i * 4);
    o[0] = __floats2half2_rn(v.x, v.y);
    o[1] = __floats2half2_rn(v.z, v.w);
}

// ---------------------------------------------------------------------------
// HMMA fp16 GEMM-NT: C[m,n] = sum_k A[m,k]*Bw[n,k], fp32 accumulate.
// 256x128 block, BK=32, 4-stage cp.async, 256 threads (8 warps, 4x2 grid).
// Warp tile 64x64: 4 m16-frags x 8 n8-frags, 8 MMA per ldmatrix.x4.
// mode 0: C fp32 row-major [M,N]
// mode 1: C fp32 scatter [B,NH,S,HD]   (BN=128 = one head per column block)
// mode 3: C fp16 scatter [B,NH,S,HD]
// ---------------------------------------------------------------------------
#define PITCHB 80
#define GSTAGES 4
#define A_BYTES (256 * PITCHB)               // 20480
#define BB_BYTES (128 * PITCHB)              // 10240
#define STAGE_BYTES (A_BYTES + BB_BYTES)     // 30720
#define GEMM_DSMEM (GSTAGES * STAGE_BYTES)   // 122880

__device__ __forceinline__ void gemm_fill(uint32_t sA, uint32_t sB,
                                          const __half* A, const __half* Bw,
                                          int m0, int n0, int K, int k0, int tid) {
#pragma unroll
    for (int i = 0; i < 4; i++) {            // A: 256 rows x 4 chunks
        int v = tid + i * 256;
        int row = v >> 2, c = v & 3;
        uint32_t off = (uint32_t)row * PITCHB + (uint32_t)c * 16;
        cp_async16(sA + off, A + (size_t)(m0 + row) * K + k0 + c * 8);
    }
#pragma unroll
    for (int i = 0; i < 2; i++) {            // B: 128 rows x 4 chunks
        int v = tid + i * 256;
        int row = v >> 2, c = v & 3;
        uint32_t off = (uint32_t)row * PITCHB + (uint32_t)c * 16;
        cp_async16(sB + off, Bw + (size_t)(n0 + row) * K + k0 + c * 8);
    }
    CP_COMMIT();
}

__global__ __launch_bounds__(256, 1)
void gemm_hmma_kernel(const __half* __restrict__ A, const __half* __restrict__ Bw,
                      float* __restrict__ C, int M, int N, int K,
                      int mode, int NH) {
    extern __shared__ __align__(128) char dsm[];
    uint32_t sBase = smem_u32(dsm);
    int tid = threadIdx.x;
    int wid = tid >> 5, l = tid & 31;
    int warpM = wid >> 1, warpN = wid & 1;
    int m0 = blockIdx.y * 256, n0 = blockIdx.x * 128;
    int KT = K >> 5;

#pragma unroll
    for (int c = 0; c < GSTAGES - 1; c++) {
        uint32_t st = sBase + c * STAGE_BYTES;
        gemm_fill(st, st + A_BYTES, A, Bw, m0, n0, K, c * 32, tid);
    }

    float acc[4][8][4];
#pragma unroll
    for (int mt = 0; mt < 4; mt++)
#pragma unroll
        for (int nt = 0; nt < 8; nt++)
#pragma unroll
            for (int i = 0; i < 4; i++) acc[mt][nt][i] = 0.f;

    uint32_t lOff = (uint32_t)(l & 15) * PITCHB + (uint32_t)(l >> 4) * 16;

    for (int kt = 0; kt < KT; kt++) {
        if (kt < KT - 2) cp_wait<2>();
        else if (kt == KT - 2) cp_wait<1>();
        else cp_wait<0>();
        __syncthreads();

        int nk = kt + GSTAGES - 1;
        if (nk < KT) {
            uint32_t st = sBase + (uint32_t)(nk % GSTAGES) * STAGE_BYTES;
            gemm_fill(st, st + A_BYTES, A, Bw, m0, n0, K, nk * 32, tid);
        }

        uint32_t stA = sBase + (uint32_t)(kt % GSTAGES) * STAGE_BYTES;
        uint32_t stB = stA + A_BYTES;
        uint32_t aBase = stA + (uint32_t)(warpM * 64) * PITCHB + lOff;
        uint32_t bBase = stB + (uint32_t)(warpN * 64) * PITCHB + lOff;

#pragma unroll
        for (int ks = 0; ks < 2; ks++) {
            uint32_t kbyte = ks * 32;
            uint32_t ar[4][4], br[4][4];
#pragma unroll
            for (int mt = 0; mt < 4; mt++)
                ldsm_x4(ar[mt], aBase + (uint32_t)(mt * 16) * PITCHB + kbyte);
#pragma unroll
            for (int g = 0; g < 4; g++)
                ldsm_x4(br[g], bBase + (uint32_t)(g * 16) * PITCHB + kbyte);
#pragma unroll
            for (int mt = 0; mt < 4; mt++)
#pragma unroll
                for (int g = 0; g < 4; g++) {
                    uint32_t b0[2] = {br[g][0], br[g][2]};
                    uint32_t b1[2] = {br[g][1], br[g][3]};
                    mma16816(acc[mt][2 * g], ar[mt], b0);
                    mma16816(acc[mt][2 * g + 1], ar[mt], b1);
                }
        }
    }

    int rl0 = warpM * 64 + (l >> 2);
    int cl0 = warpN * 64 + (l & 3) * 2;
    if (mode == 3) {
        int b = m0 / S_;
        int srow = m0 % S_;
        int head = n0 >> 7;
        __half* Cb = (__half*)C + ((size_t)(b * NH + head) * S_ + srow) * HD_;
#pragma unroll
        for (int mt = 0; mt < 4; mt++)
#pragma unroll
            for (int nt = 0; nt < 8; nt++) {
                __half* d0 = Cb + (size_t)(rl0 + mt * 16) * HD_ + cl0 + nt * 8;
                __half* d1 = d0 + (size_t)8 * HD_;
                *(__half2*)d0 = __floats2half2_rn(acc[mt][nt][0], acc[mt][nt][1]);
                *(__half2*)d1 = __floats2half2_rn(acc[mt][nt][2], acc[mt][nt][3]);
            }
        return;
    }
    float* Cb;
    int rstride;
    if (mode == 0) {
        Cb = C + (size_t)m0 * N + n0;
        rstride = N;
    } else {
        int b = m0 / S_;
        int srow = m0 % S_;
        int head = n0 >> 7;
        Cb = C + ((size_t)(b * NH + head) * S_ + srow) * HD_;
        rstride = HD_;
    }
#pragma unroll
    for (int mt = 0; mt < 4; mt++)
#pragma unroll
        for (int nt = 0; nt < 8; nt++) {
            float* d0 = Cb + (size_t)(rl0 + mt * 16) * rstride + cl0 + nt * 8;
            float* d1 = d0 + (size_t)8 * rstride;
            *(float2*)d0 = make_float2(acc[mt][nt][0], acc[mt][nt][1]);
            *(float2*)d1 = make_float2(acc[mt][nt][2], acc[mt][nt][3]);
        }
}

// ---------------------------------------------------------------------------
// RoPE tables (double-precision angles for accuracy)
// ---------------------------------------------------------------------------
__global__ void rope_table_kernel(const int* __restrict__ pos_ids) {
    int idx = blockIdx.x * blockDim.x + threadIdx.x;
    if (idx >= B_ * S_ * 64) return;
    int i = idx & 63;
    int bs = idx >> 6;
    int p = pos_ids[bs];
    double invf = exp2(-((double)(2 * i) / 128.0) * 13.287712379549449);
    double ang = (double)p * invf;
    double sd, cd;
    sincos(ang, &sd, &cd);
    g_cos[idx] = (float)cd;
    g_sin[idx] = (float)sd;
}

// RoPE apply fp32 -> fp16 (optionally pre-scaled for Q)
__global__ void rope_half_kernel(const float* __restrict__ T, __half* __restrict__ Th,
                                 int NH, float scale) {
    int gid = blockIdx.x * blockDim.x + threadIdx.x;
    int total = B_ * NH * S_ * 64;
    if (gid >= total) return;
    int i = gid & 63;
    int s = (gid >> 6) & (S_ - 1);
    int rest = gid >> 17;
    int h = rest % NH;
    int b = rest / NH;
    size_t off = ((size_t)((b * NH + h) * S_ + s)) * HD_;
    const float* p = T + off;
    __half* q = Th + off;
    int ti = (b * S_ + s) * 64 + i;
    float c = g_cos[ti], sn = g_sin[ti];
    float x1 = p[i], x2 = p[i + 64];
    q[i]      = __float2half((x1 * c - x2 * sn) * scale);
    q[i + 64] = __float2half((x2 * c + x1 * sn) * scale);
}

// ---------------------------------------------------------------------------
// Flash attention, HMMA fp16, causal. Br=Bc=64, 128 threads (4 warps).
// Warp w owns q-rows [w*16, w*16+16). P stays in registers (S frag == A frag).
// K/V double-buffered cp.async. Q pre-scaled by 1/sqrt(HD) in rope_half.
// Output fp16 [B,S,H,HD].
// ---------------------------------------------------------------------------
#define FPITCH 272                       // bytes per 128-half row (136 halves)
#define FTILE (64 * FPITCH)              // 17408
#define FLASH_DSMEM (5 * FTILE)          // Q + 2*K + 2*V = 87040

__device__ __forceinline__ void flash_fill_tile(uint32_t sbuf, const __half* src,
                                                int tid) {
#pragma unroll
    for (int i = 0; i < 8; i++) {
        int v = tid + i * 128;           // 0..1023
        int row = v >> 4, c = v & 15;
        cp_async16(sbuf + (uint32_t)row * FPITCH + (uint32_t)c * 16,
                   src + (size_t)row * HD_ + c * 8);
    }
}

__global__ __launch_bounds__(128)
void flash_hmma_kernel(const __half* __restrict__ Q, const __half* __restrict__ Kg,
                       const __half* __restrict__ Vg, __half* __restrict__ AO) {
    extern __shared__ __align__(128) char dsm[];
    uint32_t sQ = smem_u32(dsm);
    uint32_t sK0 = sQ + FTILE;           // stages: K0,K1,V0,V1
    uint32_t sV0 = sQ + 3 * FTILE;

    int tid = threadIdx.x;
    int w = tid >> 5, l = tid & 31;
    int qt = gridDim.x - 1 - blockIdx.x;   // heavy tiles first
    int bh = blockIdx.y;
    int b = bh / H_, h = bh % H_;
    int kh = h / (H_ / KV_);

    const __half* Qp = Q + ((size_t)(b * H_ + h) * S_ + qt * 64) * HD_;
    const __half* Kp = Kg + ((size_t)(b * KV_ + kh) * S_) * HD_;
    const __half* Vp = Vg + ((size_t)(b * KV_ + kh) * S_) * HD_;

    int ntiles = qt + 1;

    // prologue: Q + tile 0
    flash_fill_tile(sQ, Qp, tid);
    flash_fill_tile(sK0, Kp, tid);
    flash_fill_tile(sV0, Vp, tid);
    CP_COMMIT();

    uint32_t laneOff = (uint32_t)(l & 15) * FPITCH + (uint32_t)(l >> 4) * 16;

    uint32_t Qf[8][4];
    float O[16][4];
#pragma unroll
    for (int nf = 0; nf < 16; nf++)
#pragma unroll
        for (int i = 0; i < 4; i++) O[nf][i] = 0.f;
    float m0 = -1e30f, m1 = -1e30f, l0 = 0.f, l1 = 0.f;

    int lq = l >> 2;                      // 0..7 (row within band)
    int lc2 = (l & 3) * 2;                // col pair base

    for (int j = 0; j < ntiles; j++) {
        int buf = j & 1;
        if (j + 1 < ntiles) {
            int nbuf = (j + 1) & 1;
            flash_fill_tile(sK0 + nbuf * FTILE, Kp + (size_t)(j + 1) * 64 * HD_, tid);
            flash_fill_tile(sV0 + nbuf * FTILE, Vp + (size_t)(j + 1) * 64 * HD_, tid);
            CP_COMMIT();
            cp_wait<1>();
        } else {
            cp_wait<0>();
        }
        __syncthreads();

        if (j == 0) {
            uint32_t qb = sQ + (uint32_t)(w * 16) * FPITCH + laneOff;
#pragma unroll
            for (int kc = 0; kc < 8; kc++) ldsm_x4(Qf[kc], qb + kc * 32);
        }

        // ---- S = Q K^T (scaled already) ----
        float sacc[8][4];
#pragma unroll
        for (int nf = 0; nf < 8; nf++)
#pragma unroll
            for (int i = 0; i < 4; i++) sacc[nf][i] = 0.f;

        uint32_t kb = sK0 + (uint32_t)buf * FTILE + laneOff;
#pragma unroll
        for (int kc = 0; kc < 8; kc++) {
#pragma unroll
            for (int g = 0; g < 4; g++) {
                uint32_t r[4];
                ldsm_x4(r, kb + (uint32_t)(g * 16) * FPITCH + kc * 32);
                uint32_t b0[2] = {r[0], r[2]}, b1[2] = {r[1], r[3]};
                mma16816(sacc[2 * g], Qf[kc], b0);
                mma16816(sacc[2 * g + 1], Qf[kc], b1);
            }
        }

        // ---- causal mask (diagonal tile only) ----
        if (j == qt) {
            int lr0 = w * 16 + lq, lr1 = lr0 + 8;
#pragma unroll
            for (int nf = 0; nf < 8; nf++) {
                int c0 = nf * 8 + lc2;
                if (c0 > lr0) sacc[nf][0] = -1e30f;
                if (c0 + 1 > lr0) sacc[nf][1] = -1e30f;
                if (c0 > lr1) sacc[nf][2] = -1e30f;
                if (c0 + 1 > lr1) sacc[nf][3] = -1e30f;
            }
        }

        // ---- online softmax ----
        float mx0 = -1e30f, mx1 = -1e30f;
#pragma unroll
        for (int nf = 0; nf < 8; nf++) {
            mx0 = fmaxf(mx0, fmaxf(sacc[nf][0], sacc[nf][1]));
            mx1 = fmaxf(mx1, fmaxf(sacc[nf][2], sacc[nf][3]));
        }
        mx0 = fmaxf(mx0, __shfl_xor_sync(0xffffffffu, mx0, 1));
        mx0 = fmaxf(mx0, __shfl_xor_sync(0xffffffffu, mx0, 2));
        mx1 = fmaxf(mx1, __shfl_xor_sync(0xffffffffu, mx1, 1));
        mx1 = fmaxf(mx1, __shfl_xor_sync(0xffffffffu, mx1, 2));
        float m0n = fmaxf(m0, mx0), m1n = fmaxf(m1, mx1);
        float f0 = __expf(m0 - m0n), f1 = __expf(m1 - m1n);

        uint32_t Pf[4][4];
        float s0 = 0.f, s1 = 0.f;
#pragma unroll
        for (int kc = 0; kc < 4; kc++) {
            float pa = __expf(sacc[2 * kc][0] - m0n);
            float pb = __expf(sacc[2 * kc][1] - m0n);
            float pc = __expf(sacc[2 * kc][2] - m1n);
            float pd = __expf(sacc[2 * kc][3] - m1n);
            float pe = __expf(sacc[2 * kc + 1][0] - m0n);
            float pf = __expf(sacc[2 * kc + 1][1] - m0n);
            float pg = __expf(sacc[2 * kc + 1][2] - m1n);
            float ph = __expf(sacc[2 * kc + 1][3] - m1n);
            s0 += pa + pb + pe + pf;
            s1 += pc + pd + pg + ph;
            Pf[kc][0] = h2_as_u32(__floats2half2_rn(pa, pb));
            Pf[kc][1] = h2_as_u32(__floats2half2_rn(pc, pd));
            Pf[kc][2] = h2_as_u32(__floats2half2_rn(pe, pf));
            Pf[kc][3] = h2_as_u32(__floats2half2_rn(pg, ph));
        }
        l0 = l0 * f0 + s0;
        l1 = l1 * f1 + s1;
        m0 = m0n; m1 = m1n;

        // rescale O
#pragma unroll
        for (int nf = 0; nf < 16; nf++) {
            O[nf][0] *= f0; O[nf][1] *= f0;
            O[nf][2] *= f1; O[nf][3] *= f1;
        }

        // ---- O += P V ----
        uint32_t vb = sV0 + (uint32_t)buf * FTILE + laneOff;
#pragma unroll
        for (int kc = 0; kc < 4; kc++) {
#pragma unroll
            for (int g = 0; g < 8; g++) {
                uint32_t r[4];
                ldsm_x4_t(r, vb + (uint32_t)(kc * 16) * FPITCH + g * 32);
                uint32_t b0[2] = {r[0], r[1]}, b1[2] = {r[2], r[3]};
                mma16816(O[2 * g], Pf[kc], b0);
                mma16816(O[2 * g + 1], Pf[kc], b1);
            }
        }
        __syncthreads();
    }

    // reduce row sums over quad
    l0 += __shfl_xor_sync(0xffffffffu, l0, 1);
    l0 += __shfl_xor_sync(0xffffffffu, l0, 2);
    l1 += __shfl_xor_sync(0xffffffffu, l1, 1);
    l1 += __shfl_xor_sync(0xffffffffu, l1, 2);
    float inv0 = 1.0f / l0, inv1 = 1.0f / l1;

    int row0 = qt * 64 + w * 16 + lq;
    __half* base0 = AO + ((size_t)(b * S_ + row0) * H_ + h) * HD_;
    __half* base1 = AO + ((size_t)(b * S_ + row0 + 8) * H_ + h) * HD_;
#pragma unroll
    for (int nf = 0; nf < 16; nf++) {
        int c0 = nf * 8 + lc2;
        *(__half2*)(base0 + c0) = __floats2half2_rn(O[nf][0] * inv0, O[nf][1] * inv0);
        *(__half2*)(base1 + c0) = __floats2half2_rn(O[nf][2] * inv1, O[nf][3] * inv1);
    }
}

// ---------------------------------------------------------------------------
extern "C" void kernel_launch(void* const* d_in, const int* in_sizes, int n_in,
                              void* d_out, int out_size) {
    const float* hs  = (const float*)d_in[0];
    const float* Wq  = (const float*)d_in[1];
    const float* Wk  = (const float*)d_in[2];
    const float* Wv  = (const float*)d_in[3];
    const float* Wo  = (const float*)d_in[4];
    const int*   pos = (const int*)d_in[5];
    float* out = (float*)d_out;

    float *gQ, *gK;
    __half *hsH, *WqH, *WkH, *WvH, *WoH, *QH, *KH, *VH, *AOH;
    cudaGetSymbolAddress((void**)&gQ, g_Q);
    cudaGetSymbolAddress((void**)&gK, g_K);
    cudaGetSymbolAddress((void**)&hsH, g_hsH);
    cudaGetSymbolAddress((void**)&WqH, g_WqH);
    cudaGetSymbolAddress((void**)&WkH, g_WkH);
    cudaGetSymbolAddress((void**)&WvH, g_WvH);
    cudaGetSymbolAddress((void**)&WoH, g_WoH);
    cudaGetSymbolAddress((void**)&QH, g_QH);
    cudaGetSymbolAddress((void**)&KH, g_KH);
    cudaGetSymbolAddress((void**)&VH, g_VH);
    cudaGetSymbolAddress((void**)&AOH, g_AOH);

    cudaFuncSetAttribute(gemm_hmma_kernel,
                         cudaFuncAttributeMaxDynamicSharedMemorySize, GEMM_DSMEM);
    cudaFuncSetAttribute(flash_hmma_kernel,
                         cudaFuncAttributeMaxDynamicSharedMemorySize, FLASH_DSMEM);

    // RoPE tables
    rope_table_kernel<<<(B_ * S_ * 64 + 255) / 256, 256>>>(pos);

    // fp32 -> fp16 conversions
    const int nHS = B_ * S_ * D_ / 4, nWq = H_ * HD_ * D_ / 4,
              nWk = KV_ * HD_ * D_ / 4, nWo = D_ * H_ * HD_ / 4;
    f32_to_f16_kernel<<<nHS / 256, 256>>>(hs, hsH, nHS);
    f32_to_f16_kernel<<<nWq / 256, 256>>>(Wq, WqH, nWq);
    f32_to_f16_kernel<<<nWk / 256, 256>>>(Wk, WkH, nWk);
    f32_to_f16_kernel<<<nWk / 256, 256>>>(Wv, WvH, nWk);
    f32_to_f16_kernel<<<nWo / 256, 256>>>(Wo, WoH, nWo);

    // Projections (M = B*S = 4096, K = D = 4096), 256x128 blocks
    gemm_hmma_kernel<<<dim3(H_ * HD_ / 128, (B_ * S_) / 256), 256, GEMM_DSMEM>>>(
        hsH, WqH, gQ, B_ * S_, H_ * HD_, D_, 1, H_);
    gemm_hmma_kernel<<<dim3(KV_ * HD_ / 128, (B_ * S_) / 256), 256, GEMM_DSMEM>>>(
        hsH, WkH, gK, B_ * S_, KV_ * HD_, D_, 1, KV_);
    gemm_hmma_kernel<<<dim3(KV_ * HD_ / 128, (B_ * S_) / 256), 256, GEMM_DSMEM>>>(
        hsH, WvH, (float*)VH, B_ * S_, KV_ * HD_, D_, 3, KV_);

    // RoPE -> fp16 (Q pre-scaled by 1/sqrt(HD))
    rope_half_kernel<<<(B_ * H_ * S_ * 64) / 256, 256>>>(gQ, QH, H_,
                                                         0.08838834764831845f);
    rope_half_kernel<<<(B_ * KV_ * S_ * 64) / 256, 256>>>(gK, KH, KV_, 1.0f);

    // Flash attention (HMMA, causal)
    flash_hmma_kernel<<<dim3(S_ / 64, B_ * H_), 128, FLASH_DSMEM>>>(
        QH, KH, VH, AOH);

    // Output projection
    gemm_hmma_kernel<<<dim3(D_ / 128, (B_ * S_) / 256), 256, GEMM_DSMEM>>>(
        AOH, WoH, out, B_ * S_, D_, H_ * HD_, 0, 0);
}

// round 10
// speedup vs baseline: 1.1783x; 1.1783x over previous
#include <cuda_runtime.h>
#include <cuda_fp16.h>
#include <math.h>
#include <cstdint>

// Problem constants
#define B_ 2
#define S_ 2048
#define D_ 4096
#define H_ 32
#define KV_ 8
#define HD_ 128

// ---------------------------------------------------------------------------
// Scratch (static __device__ per allocation rules)
// ---------------------------------------------------------------------------
__device__ float g_Q[(size_t)B_ * H_ * S_ * HD_];    // [B,H,S,HD] fp32 pre-rope
__device__ float g_K[(size_t)B_ * KV_ * S_ * HD_];
__device__ float g_cos[(size_t)B_ * S_ * 64];
__device__ float g_sin[(size_t)B_ * S_ * 64];
// fp16 tensors
__device__ __half g_hsH[(size_t)B_ * S_ * D_];
__device__ __half g_WqH[(size_t)H_ * HD_ * D_];
__device__ __half g_WkH[(size_t)KV_ * HD_ * D_];
__device__ __half g_WvH[(size_t)KV_ * HD_ * D_];
__device__ __half g_WoH[(size_t)D_ * H_ * HD_];
__device__ __half g_QH[(size_t)B_ * H_ * S_ * HD_];  // roped, pre-scaled
__device__ __half g_KH[(size_t)B_ * KV_ * S_ * HD_]; // roped
__device__ __half g_VH[(size_t)B_ * KV_ * S_ * HD_]; // from GEMM epilogue
__device__ __half g_AOH[(size_t)B_ * S_ * H_ * HD_]; // flash out [B,S,H,HD]

// ---------------------------------------------------------------------------
// Helpers
// ---------------------------------------------------------------------------
__device__ __forceinline__ uint32_t smem_u32(const void* p) {
    uint32_t a;
    asm("{ .reg .u64 t; cvta.to.shared.u64 t, %1; cvt.u32.u64 %0, t; }"
        : "=r"(a) : "l"(p));
    return a;
}
__device__ __forceinline__ uint32_t h2_as_u32(__half2 h) {
    union { __half2 h; uint32_t u; } cvt;
    cvt.h = h;
    return cvt.u;
}
__device__ __forceinline__ void cp_async16(uint32_t saddr, const void* g) {
    asm volatile("cp.async.cg.shared.global [%0], [%1], 16;" :: "r"(saddr), "l"(g));
}
#define CP_COMMIT() asm volatile("cp.async.commit_group;" ::: "memory")
template <int N>
__device__ __forceinline__ void cp_wait() {
    asm volatile("cp.async.wait_group %0;" :: "n"(N) : "memory");
}
__device__ __forceinline__ void ldsm_x4(uint32_t* r, uint32_t addr) {
    asm volatile("ldmatrix.sync.aligned.m8n8.x4.shared.b16 {%0,%1,%2,%3}, [%4];"
                 : "=r"(r[0]), "=r"(r[1]), "=r"(r[2]), "=r"(r[3]) : "r"(addr));
}
__device__ __forceinline__ void ldsm_x4_t(uint32_t* r, uint32_t addr) {
    asm volatile("ldmatrix.sync.aligned.m8n8.x4.trans.shared.b16 {%0,%1,%2,%3}, [%4];"
                 : "=r"(r[0]), "=r"(r[1]), "=r"(r[2]), "=r"(r[3]) : "r"(addr));
}
__device__ __forceinline__ void ldsm_x2(uint32_t* r, uint32_t addr) {
    asm volatile("ldmatrix.sync.aligned.m8n8.x2.shared.b16 {%0,%1}, [%2];"
                 : "=r"(r[0]), "=r"(r[1]) : "r"(addr));
}
__device__ __forceinline__ void mma16816(float* c, const uint32_t* a, const uint32_t* b) {
    asm volatile(
        "mma.sync.aligned.m16n8k16.row.col.f32.f16.f16.f32 "
        "{%0,%1,%2,%3}, {%4,%5,%6,%7}, {%8,%9}, {%0,%1,%2,%3};"
        : "+f"(c[0]), "+f"(c[1]), "+f"(c[2]), "+f"(c[3])
        : "r"(a[0]), "r"(a[1]), "r"(a[2]), "r"(a[3]), "r"(b[0]), "r"(b[1]));
}

// ---------------------------------------------------------------------------
// fp32 -> fp16 conversion (4 elems/thread)
// ---------------------------------------------------------------------------
__global__ void f32_to_f16_kernel(const float* __restrict__ in,
                                  __half* __restrict__ out, int n4) {
    int i = blockIdx.x * blockDim.x + threadIdx.x;
    if (i >= n4) return;
    float4 v = *(const float4*)(in + (size_t)i * 4);
    __half2* o = (__half2*)(out + (size_t)i * 4);
    o[0] = __floats2half2_rn(v.x, v.y);
    o[1] = __floats2half2_rn(v.z, v.w);
}

// ---------------------------------------------------------------------------
// HMMA GEMM core (R8-proven): 128x128 tile, BK=32, 4-stage cp.async,
// 256 threads (8 warps, 2x4), warp tile 64x32.
// ---------------------------------------------------------------------------
#define PITCHB 80
#define GSTAGES 4
#define OP_BYTES (128 * PITCHB)
#define STAGE_BYTES (2 * OP_BYTES)
#define GEMM_DSMEM (GSTAGES * STAGE_BYTES)

__device__ __forceinline__ void gemm_fill(uint32_t sA, uint32_t sB,
                                          const __half* A, const __half* Bw,
                                          int m0, int n0, int K, int k0, int tid) {
#pragma unroll
    for (int i = 0; i < 2; i++) {
        int v = tid + i * 256;
        int row = v >> 2, c = v & 3;
        uint32_t off = (uint32_t)row * PITCHB + (uint32_t)c * 16;
        cp_async16(sA + off, A + (size_t)(m0 + row) * K + k0 + c * 8);
        cp_async16(sB + off, Bw + (size_t)(n0 + row) * K + k0 + c * 8);
    }
    CP_COMMIT();
}

// Mainloop producing acc[4][4][4]; caller handles epilogue.
__device__ __forceinline__ void gemm_mainloop(const __half* A, const __half* Bw,
                                              int m0, int n0, int K,
                                              uint32_t sBase, int tid,
                                              float acc[4][4][4]) {
    int wid = tid >> 5, l = tid & 31;
    int warpM = wid >> 2, warpN = wid & 3;
    int KT = K >> 5;

#pragma unroll
    for (int c = 0; c < GSTAGES - 1; c++) {
        uint32_t st = sBase + c * STAGE_BYTES;
        gemm_fill(st, st + OP_BYTES, A, Bw, m0, n0, K, c * 32, tid);
    }

    uint32_t aOff = (uint32_t)(l & 15) * PITCHB + (uint32_t)(l >> 4) * 16;
    uint32_t bOff = (uint32_t)(l & 7) * PITCHB + (uint32_t)((l >> 3) & 1) * 16;

    for (int kt = 0; kt < KT; kt++) {
        if (kt < KT - 2) cp_wait<2>();
        else if (kt == KT - 2) cp_wait<1>();
        else cp_wait<0>();
        __syncthreads();

        int nk = kt + GSTAGES - 1;
        if (nk < KT) {
            uint32_t st = sBase + (uint32_t)(nk % GSTAGES) * STAGE_BYTES;
            gemm_fill(st, st + OP_BYTES, A, Bw, m0, n0, K, nk * 32, tid);
        }

        uint32_t stA = sBase + (uint32_t)(kt % GSTAGES) * STAGE_BYTES;
        uint32_t stB = stA + OP_BYTES;
        uint32_t aBase = stA + (uint32_t)(warpM * 64) * PITCHB + aOff;
        uint32_t bBase = stB + (uint32_t)(warpN * 32) * PITCHB + bOff;

#pragma unroll
        for (int ks = 0; ks < 2; ks++) {
            uint32_t kbyte = ks * 32;
            uint32_t ar[4][4], br[4][2];
#pragma unroll
            for (int mt = 0; mt < 4; mt++)
                ldsm_x4(ar[mt], aBase + (uint32_t)(mt * 16) * PITCHB + kbyte);
#pragma unroll
            for (int nt = 0; nt < 4; nt++)
                ldsm_x2(br[nt], bBase + (uint32_t)(nt * 8) * PITCHB + kbyte);
#pragma unroll
            for (int mt = 0; mt < 4; mt++)
#pragma unroll
                for (int nt = 0; nt < 4; nt++)
                    mma16816(acc[mt][nt], ar[mt], br[nt]);
        }
    }
}

// Fused QKV projection: blockIdx.x in [0,48) selects weight/output segment.
//   [0,32)  : Wq -> g_Q  (fp32 scatter [B,32,S,HD])
//   [32,40) : Wk -> g_K  (fp32 scatter [B,8,S,HD])
//   [40,48) : Wv -> g_VH (fp16 scatter [B,8,S,HD])
__global__ __launch_bounds__(256, 2)
void qkv_hmma_kernel(const __half* __restrict__ A,
                     const __half* __restrict__ Wq, const __half* __restrict__ Wk,
                     const __half* __restrict__ Wv,
                     float* __restrict__ Qo, float* __restrict__ Ko,
                     __half* __restrict__ Vo) {
    extern __shared__ __align__(128) char dsm[];
    uint32_t sBase = smem_u32(dsm);
    int tid = threadIdx.x;
    int bx = blockIdx.x;
    int m0 = blockIdx.y * 128;

    const __half* Bw;
    int head;
    int seg;                         // 0=Q, 1=K, 2=V
    if (bx < 32)      { Bw = Wq; head = bx;      seg = 0; }
    else if (bx < 40) { Bw = Wk; head = bx - 32; seg = 1; }
    else              { Bw = Wv; head = bx - 40; seg = 2; }
    int n0 = head * 128;
    int NH = (seg == 0) ? H_ : KV_;

    float acc[4][4][4];
#pragma unroll
    for (int mt = 0; mt < 4; mt++)
#pragma unroll
        for (int nt = 0; nt < 4; nt++)
#pragma unroll
            for (int i = 0; i < 4; i++) acc[mt][nt][i] = 0.f;

    gemm_mainloop(A, Bw, m0, n0, D_, sBase, tid, acc);

    int wid = tid >> 5, l = tid & 31;
    int warpM = wid >> 2, warpN = wid & 3;
    int rl0 = warpM * 64 + (l >> 2);
    int cl0 = warpN * 32 + (l & 3) * 2;
    int b = m0 / S_;
    int srow = m0 % S_;

    if (seg == 2) {
        __half* Cb = Vo + ((size_t)(b * NH + head) * S_ + srow) * HD_;
#pragma unroll
        for (int mt = 0; mt < 4; mt++)
#pragma unroll
            for (int nt = 0; nt < 4; nt++) {
                __half* d0 = Cb + (size_t)(rl0 + mt * 16) * HD_ + cl0 + nt * 8;
                __half* d1 = d0 + (size_t)8 * HD_;
                *(__half2*)d0 = __floats2half2_rn(acc[mt][nt][0], acc[mt][nt][1]);
                *(__half2*)d1 = __floats2half2_rn(acc[mt][nt][2], acc[mt][nt][3]);
            }
    } else {
        float* Cb = ((seg == 0) ? Qo : Ko) +
                    ((size_t)(b * NH + head) * S_ + srow) * HD_;
#pragma unroll
        for (int mt = 0; mt < 4; mt++)
#pragma unroll
            for (int nt = 0; nt < 4; nt++) {
                float* d0 = Cb + (size_t)(rl0 + mt * 16) * HD_ + cl0 + nt * 8;
                float* d1 = d0 + (size_t)8 * HD_;
                *(float2*)d0 = make_float2(acc[mt][nt][0], acc[mt][nt][1]);
                *(float2*)d1 = make_float2(acc[mt][nt][2], acc[mt][nt][3]);
            }
    }
}

// Plain GEMM (O projection): C fp32 row-major [M,N].
__global__ __launch_bounds__(256, 2)
void gemm_hmma_kernel(const __half* __restrict__ A, const __half* __restrict__ Bw,
                      float* __restrict__ C, int M, int N, int K) {
    extern __shared__ __align__(128) char dsm[];
    uint32_t sBase = smem_u32(dsm);
    int tid = threadIdx.x;
    int m0 = blockIdx.y * 128, n0 = blockIdx.x * 128;

    float acc[4][4][4];
#pragma unroll
    for (int mt = 0; mt < 4; mt++)
#pragma unroll
        for (int nt = 0; nt < 4; nt++)
#pragma unroll
            for (int i = 0; i < 4; i++) acc[mt][nt][i] = 0.f;

    gemm_mainloop(A, Bw, m0, n0, K, sBase, tid, acc);

    int wid = tid >> 5, l = tid & 31;
    int warpM = wid >> 2, warpN = wid & 3;
    int rl0 = warpM * 64 + (l >> 2);
    int cl0 = warpN * 32 + (l & 3) * 2;
    float* Cb = C + (size_t)m0 * N + n0;
#pragma unroll
    for (int mt = 0; mt < 4; mt++)
#pragma unroll
        for (int nt = 0; nt < 4; nt++) {
            float* d0 = Cb + (size_t)(rl0 + mt * 16) * N + cl0 + nt * 8;
            float* d1 = d0 + (size_t)8 * N;
            *(float2*)d0 = make_float2(acc[mt][nt][0], acc[mt][nt][1]);
            *(float2*)d1 = make_float2(acc[mt][nt][2], acc[mt][nt][3]);
        }
}

// ---------------------------------------------------------------------------
// RoPE tables (double-precision angles for accuracy)
// ---------------------------------------------------------------------------
__global__ void rope_table_kernel(const int* __restrict__ pos_ids) {
    int idx = blockIdx.x * blockDim.x + threadIdx.x;
    if (idx >= B_ * S_ * 64) return;
    int i = idx & 63;
    int bs = idx >> 6;
    int p = pos_ids[bs];
    double invf = exp2(-((double)(2 * i) / 128.0) * 13.287712379549449);
    double ang = (double)p * invf;
    double sd, cd;
    sincos(ang, &sd, &cd);
    g_cos[idx] = (float)cd;
    g_sin[idx] = (float)sd;
}

// RoPE apply fp32 -> fp16 (optionally pre-scaled for Q)
__global__ void rope_half_kernel(const float* __restrict__ T, __half* __restrict__ Th,
                                 int NH, float scale) {
    int gid = blockIdx.x * blockDim.x + threadIdx.x;
    int total = B_ * NH * S_ * 64;
    if (gid >= total) return;
    int i = gid & 63;
    int s = (gid >> 6) & (S_ - 1);
    int rest = gid >> 17;
    int h = rest % NH;
    int b = rest / NH;
    size_t off = ((size_t)((b * NH + h) * S_ + s)) * HD_;
    const float* p = T + off;
    __half* q = Th + off;
    int ti = (b * S_ + s) * 64 + i;
    float c = g_cos[ti], sn = g_sin[ti];
    float x1 = p[i], x2 = p[i + 64];
    q[i]      = __float2half((x1 * c - x2 * sn) * scale);
    q[i + 64] = __float2half((x2 * c + x1 * sn) * scale);
}

// ---------------------------------------------------------------------------
// Flash attention, HMMA fp16, causal. Br=Bc=64, 128 threads (4 warps).
// (R8-proven, unchanged)
// ---------------------------------------------------------------------------
#define FPITCH 272
#define FTILE (64 * FPITCH)
#define FLASH_DSMEM (5 * FTILE)

__device__ __forceinline__ void flash_fill_tile(uint32_t sbuf, const __half* src,
                                                int tid) {
#pragma unroll
    for (int i = 0; i < 8; i++) {
        int v = tid + i * 128;
        int row = v >> 4, c = v & 15;
        cp_async16(sbuf + (uint32_t)row * FPITCH + (uint32_t)c * 16,
                   src + (size_t)row * HD_ + c * 8);
    }
}

__global__ __launch_bounds__(128)
void flash_hmma_kernel(const __half* __restrict__ Q, const __half* __restrict__ Kg,
                       const __half* __restrict__ Vg, __half* __restrict__ AO) {
    extern __shared__ __align__(128) char dsm[];
    uint32_t sQ = smem_u32(dsm);
    uint32_t sK0 = sQ + FTILE;
    uint32_t sV0 = sQ + 3 * FTILE;

    int tid = threadIdx.x;
    int w = tid >> 5, l = tid & 31;
    int qt = gridDim.x - 1 - blockIdx.x;
    int bh = blockIdx.y;
    int b = bh / H_, h = bh % H_;
    int kh = h / (H_ / KV_);

    const __half* Qp = Q + ((size_t)(b * H_ + h) * S_ + qt * 64) * HD_;
    const __half* Kp = Kg + ((size_t)(b * KV_ + kh) * S_) * HD_;
    const __half* Vp = Vg + ((size_t)(b * KV_ + kh) * S_) * HD_;

    int ntiles = qt + 1;

    flash_fill_tile(sQ, Qp, tid);
    flash_fill_tile(sK0, Kp, tid);
    flash_fill_tile(sV0, Vp, tid);
    CP_COMMIT();

    uint32_t laneOff = (uint32_t)(l & 15) * FPITCH + (uint32_t)(l >> 4) * 16;

    uint32_t Qf[8][4];
    float O[16][4];
#pragma unroll
    for (int nf = 0; nf < 16; nf++)
#pragma unroll
        for (int i = 0; i < 4; i++) O[nf][i] = 0.f;
    float m0 = -1e30f, m1 = -1e30f, l0 = 0.f, l1 = 0.f;

    int lq = l >> 2;
    int lc2 = (l & 3) * 2;

    for (int j = 0; j < ntiles; j++) {
        int buf = j & 1;
        if (j + 1 < ntiles) {
            int nbuf = (j + 1) & 1;
            flash_fill_tile(sK0 + nbuf * FTILE, Kp + (size_t)(j + 1) * 64 * HD_, tid);
            flash_fill_tile(sV0 + nbuf * FTILE, Vp + (size_t)(j + 1) * 64 * HD_, tid);
            CP_COMMIT();
            cp_wait<1>();
        } else {
            cp_wait<0>();
        }
        __syncthreads();

        if (j == 0) {
            uint32_t qb = sQ + (uint32_t)(w * 16) * FPITCH + laneOff;
#pragma unroll
            for (int kc = 0; kc < 8; kc++) ldsm_x4(Qf[kc], qb + kc * 32);
        }

        float sacc[8][4];
#pragma unroll
        for (int nf = 0; nf < 8; nf++)
#pragma unroll
            for (int i = 0; i < 4; i++) sacc[nf][i] = 0.f;

        uint32_t kb = sK0 + (uint32_t)buf * FTILE + laneOff;
#pragma unroll
        for (int kc = 0; kc < 8; kc++) {
#pragma unroll
            for (int g = 0; g < 4; g++) {
                uint32_t r[4];
                ldsm_x4(r, kb + (uint32_t)(g * 16) * FPITCH + kc * 32);
                uint32_t b0[2] = {r[0], r[2]}, b1[2] = {r[1], r[3]};
                mma16816(sacc[2 * g], Qf[kc], b0);
                mma16816(sacc[2 * g + 1], Qf[kc], b1);
            }
        }

        if (j == qt) {
            int lr0 = w * 16 + lq, lr1 = lr0 + 8;
#pragma unroll
            for (int nf = 0; nf < 8; nf++) {
                int c0 = nf * 8 + lc2;
                if (c0 > lr0) sacc[nf][0] = -1e30f;
                if (c0 + 1 > lr0) sacc[nf][1] = -1e30f;
                if (c0 > lr1) sacc[nf][2] = -1e30f;
                if (c0 + 1 > lr1) sacc[nf][3] = -1e30f;
            }
        }

        float mx0 = -1e30f, mx1 = -1e30f;
#pragma unroll
        for (int nf = 0; nf < 8; nf++) {
            mx0 = fmaxf(mx0, fmaxf(sacc[nf][0], sacc[nf][1]));
            mx1 = fmaxf(mx1, fmaxf(sacc[nf][2], sacc[nf][3]));
        }
        mx0 = fmaxf(mx0, __shfl_xor_sync(0xffffffffu, mx0, 1));
        mx0 = fmaxf(mx0, __shfl_xor_sync(0xffffffffu, mx0, 2));
        mx1 = fmaxf(mx1, __shfl_xor_sync(0xffffffffu, mx1, 1));
        mx1 = fmaxf(mx1, __shfl_xor_sync(0xffffffffu, mx1, 2));
        float m0n = fmaxf(m0, mx0), m1n = fmaxf(m1, mx1);
        float f0 = __expf(m0 - m0n), f1 = __expf(m1 - m1n);

        uint32_t Pf[4][4];
        float s0 = 0.f, s1 = 0.f;
#pragma unroll
        for (int kc = 0; kc < 4; kc++) {
            float pa = __expf(sacc[2 * kc][0] - m0n);
            float pb = __expf(sacc[2 * kc][1] - m0n);
            float pc = __expf(sacc[2 * kc][2] - m1n);
            float pd = __expf(sacc[2 * kc][3] - m1n);
            float pe = __expf(sacc[2 * kc + 1][0] - m0n);
            float pf = __expf(sacc[2 * kc + 1][1] - m0n);
            float pg = __expf(sacc[2 * kc + 1][2] - m1n);
            float ph = __expf(sacc[2 * kc + 1][3] - m1n);
            s0 += pa + pb + pe + pf;
            s1 += pc + pd + pg + ph;
            Pf[kc][0] = h2_as_u32(__floats2half2_rn(pa, pb));
            Pf[kc][1] = h2_as_u32(__floats2half2_rn(pc, pd));
            Pf[kc][2] = h2_as_u32(__floats2half2_rn(pe, pf));
            Pf[kc][3] = h2_as_u32(__floats2half2_rn(pg, ph));
        }
        l0 = l0 * f0 + s0;
        l1 = l1 * f1 + s1;
        m0 = m0n; m1 = m1n;

#pragma unroll
        for (int nf = 0; nf < 16; nf++) {
            O[nf][0] *= f0; O[nf][1] *= f0;
            O[nf][2] *= f1; O[nf][3] *= f1;
        }

        uint32_t vb = sV0 + (uint32_t)buf * FTILE + laneOff;
#pragma unroll
        for (int kc = 0; kc < 4; kc++) {
#pragma unroll
            for (int g = 0; g < 8; g++) {
                uint32_t r[4];
                ldsm_x4_t(r, vb + (uint32_t)(kc * 16) * FPITCH + g * 32);
                uint32_t b0[2] = {r[0], r[1]}, b1[2] = {r[2], r[3]};
                mma16816(O[2 * g], Pf[kc], b0);
                mma16816(O[2 * g + 1], Pf[kc], b1);
            }
        }
        __syncthreads();
    }

    l0 += __shfl_xor_sync(0xffffffffu, l0, 1);
    l0 += __shfl_xor_sync(0xffffffffu, l0, 2);
    l1 += __shfl_xor_sync(0xffffffffu, l1, 1);
    l1 += __shfl_xor_sync(0xffffffffu, l1, 2);
    float inv0 = 1.0f / l0, inv1 = 1.0f / l1;

    int row0 = qt * 64 + w * 16 + lq;
    __half* base0 = AO + ((size_t)(b * S_ + row0) * H_ + h) * HD_;
    __half* base1 = AO + ((size_t)(b * S_ + row0 + 8) * H_ + h) * HD_;
#pragma unroll
    for (int nf = 0; nf < 16; nf++) {
        int c0 = nf * 8 + lc2;
        *(__half2*)(base0 + c0) = __floats2half2_rn(O[nf][0] * inv0, O[nf][1] * inv0);
        *(__half2*)(base1 + c0) = __floats2half2_rn(O[nf][2] * inv1, O[nf][3] * inv1);
    }
}

// ---------------------------------------------------------------------------
extern "C" void kernel_launch(void* const* d_in, const int* in_sizes, int n_in,
                              void* d_out, int out_size) {
    const float* hs  = (const float*)d_in[0];
    const float* Wq  = (const float*)d_in[1];
    const float* Wk  = (const float*)d_in[2];
    const float* Wv  = (const float*)d_in[3];
    const float* Wo  = (const float*)d_in[4];
    const int*   pos = (const int*)d_in[5];
    float* out = (float*)d_out;

    float *gQ, *gK;
    __half *hsH, *WqH, *WkH, *WvH, *WoH, *QH, *KH, *VH, *AOH;
    cudaGetSymbolAddress((void**)&gQ, g_Q);
    cudaGetSymbolAddress((void**)&gK, g_K);
    cudaGetSymbolAddress((void**)&hsH, g_hsH);
    cudaGetSymbolAddress((void**)&WqH, g_WqH);
    cudaGetSymbolAddress((void**)&WkH, g_WkH);
    cudaGetSymbolAddress((void**)&WvH, g_WvH);
    cudaGetSymbolAddress((void**)&WoH, g_WoH);
    cudaGetSymbolAddress((void**)&QH, g_QH);
    cudaGetSymbolAddress((void**)&KH, g_KH);
    cudaGetSymbolAddress((void**)&VH, g_VH);
    cudaGetSymbolAddress((void**)&AOH, g_AOH);

    cudaFuncSetAttribute(qkv_hmma_kernel,
                         cudaFuncAttributeMaxDynamicSharedMemorySize, GEMM_DSMEM);
    cudaFuncSetAttribute(gemm_hmma_kernel,
                         cudaFuncAttributeMaxDynamicSharedMemorySize, GEMM_DSMEM);
    cudaFuncSetAttribute(flash_hmma_kernel,
                         cudaFuncAttributeMaxDynamicSharedMemorySize, FLASH_DSMEM);

    // RoPE tables
    rope_table_kernel<<<(B_ * S_ * 64 + 255) / 256, 256>>>(pos);

    // fp32 -> fp16 conversions
    const int nHS = B_ * S_ * D_ / 4, nWq = H_ * HD_ * D_ / 4,
              nWk = KV_ * HD_ * D_ / 4, nWo = D_ * H_ * HD_ / 4;
    f32_to_f16_kernel<<<nHS / 256, 256>>>(hs, hsH, nHS);
    f32_to_f16_kernel<<<nWq / 256, 256>>>(Wq, WqH, nWq);
    f32_to_f16_kernel<<<nWk / 256, 256>>>(Wk, WkH, nWk);
    f32_to_f16_kernel<<<nWk / 256, 256>>>(Wv, WvH, nWk);
    f32_to_f16_kernel<<<nWo / 256, 256>>>(Wo, WoH, nWo);

    // Fused QKV projections (one launch, 48 x 32 = 1536 CTAs)
    qkv_hmma_kernel<<<dim3(48, (B_ * S_) / 128), 256, GEMM_DSMEM>>>(
        hsH, WqH, WkH, WvH, gQ, gK, VH);

    // RoPE -> fp16 (Q pre-scaled by 1/sqrt(HD))
    rope_half_kernel<<<(B_ * H_ * S_ * 64) / 256, 256>>>(gQ, QH, H_,
                                                         0.08838834764831845f);
    rope_half_kernel<<<(B_ * KV_ * S_ * 64) / 256, 256>>>(gK, KH, KV_, 1.0f);

    // Flash attention (HMMA, causal)
    flash_hmma_kernel<<<dim3(S_ / 64, B_ * H_), 128, FLASH_DSMEM>>>(
        QH, KH, VH, AOH);

    // Output projection
    gemm_hmma_kernel<<<dim3(D_ / 128, (B_ * S_) / 128), 256, GEMM_DSMEM>>>(
        AOH, WoH, out, B_ * S_, D_, H_ * HD_);
}